// round 12
// baseline (speedup 1.0000x reference)
#include <cuda_runtime.h>
#include <cuda_bf16.h>

// DenseRadiusGraph R10 = R8 two-kernel structure + collect-then-sort top-K.
// The serialized per-hit insertion loop (~250 instr/query) is replaced by:
//   - per-chunk smem scatter of hits at slot cnt+rank (no shuffles, no loop)
//   - one 15-stage warp bitonic sort of (dist, idx) pairs at the end
// Keys are strictly unique (idx distinct), so the lexicographic bitonic order
// is identical to the reference top_k order (lowest-index-first on dist ties).
// A correct fallback switches to the R8 insertion path if >32 hits collect
// (never triggered for this input; correctness does not rely on that).
//
// Cells: x side 10 (10 cells), y/z side 20 (5 cells) => 250 cells/graph.
// Numerics unchanged since R5: reference-rounded GEMM-form distance (no FMA,
// fixed association) for selection; direct-form non-FMA distance for w.

#define BGR   16
#define NGR   2048
#define KNB   32
#define NCX   10
#define NCYZ  5
#define NCELL (NCX * NCYZ * NCYZ)   // 250
#define TPB   256
#define QPB   (TPB / 32)
#define BT    512                    // build threads per block
#define NPT   (NGR / BT)             // 4 nodes per build thread

#define FULLM 0xffffffffu

// Scratch (device globals: no allocation allowed).
__device__ float4 g_sorted[BGR * NGR];          // cell-sorted {x,y,z,sq}
__device__ int    g_sidx[BGR * NGR];            // original local index
__device__ int    g_cellstart[BGR * NCELL + 1]; // absolute offsets (+sentinel)

__device__ __forceinline__ int clamp_x(float v) {
    int c = __float2int_rd(v * 0.1f);            // /10
    return min(NCX - 1, max(0, c));
}
__device__ __forceinline__ int clamp_yz(float v) {
    int c = __float2int_rd(v * 0.05f);           // /20
    return min(NCYZ - 1, max(0, c));
}

// ---- fused build: one CTA per graph, warp-shuffle scan (R7/R8, kept) -----

__global__ __launch_bounds__(BT) void k_build(const float* __restrict__ pos) {
    __shared__ int s_cnt[NCELL];
    __shared__ int s_woff[BT / 32];
    __shared__ int s_cur[NCELL];

    const int b    = blockIdx.x;
    const int t    = threadIdx.x;
    const int warp = t >> 5;
    const int lane = t & 31;
    const float* gp = pos + (size_t)b * NGR * 3;

    for (int i = t; i < NCELL; i += BT) s_cnt[i] = 0;
    __syncthreads();

    float px[NPT], py[NPT], pz[NPT];
    int   cid[NPT];
    #pragma unroll
    for (int k = 0; k < NPT; ++k) {
        int n = t + k * BT;
        px[k] = gp[3 * n + 0];
        py[k] = gp[3 * n + 1];
        pz[k] = gp[3 * n + 2];
        cid[k] = (clamp_yz(pz[k]) * NCYZ + clamp_yz(py[k])) * NCX + clamp_x(px[k]);
        atomicAdd(&s_cnt[cid[k]], 1);
    }
    __syncthreads();

    int v = (t < NCELL) ? s_cnt[t] : 0;
    int incl = v;
    #pragma unroll
    for (int d = 1; d < 32; d <<= 1) {
        int u = __shfl_up_sync(FULLM, incl, d);
        if (lane >= d) incl += u;
    }
    if (lane == 31) s_woff[warp] = incl;
    __syncthreads();
    if (warp == 0 && lane < BT / 32) {
        int w = s_woff[lane];
        int iw = w;
        #pragma unroll
        for (int d = 1; d < BT / 32; d <<= 1) {
            int u = __shfl_up_sync(0x0000ffffu, iw, d);
            if (lane >= d) iw += u;
        }
        s_woff[lane] = iw - w;
    }
    __syncthreads();
    if (t < NCELL) {
        int excl = incl - v + s_woff[warp];
        s_cur[t] = excl;
        g_cellstart[b * NCELL + t] = b * NGR + excl;
    }
    if (b == 0 && t == 0) g_cellstart[BGR * NCELL] = BGR * NGR;
    __syncthreads();

    const int base = b * NGR;
    #pragma unroll
    for (int k = 0; k < NPT; ++k) {
        int slot = base + atomicAdd(&s_cur[cid[k]], 1);
        float sq = __fadd_rn(__fadd_rn(__fmul_rn(px[k], px[k]),
                                       __fmul_rn(py[k], py[k])),
                             __fmul_rn(pz[k], pz[k]));
        g_sorted[slot] = make_float4(px[k], py[k], pz[k], sq);
        g_sidx[slot]   = t + k * BT;
    }
}

// ---- warp bitonic sort of 32 (dist, idx) pairs, lex ascending ------------
// Keys strictly unique => strict lex compare gives a deterministic total
// order identical to stable insertion by (dist, idx).

__device__ __forceinline__ void warp_sort32(float& kd, int& ki, int lane) {
    #pragma unroll
    for (int k = 2; k <= 32; k <<= 1) {
        #pragma unroll
        for (int j = k >> 1; j > 0; j >>= 1) {
            float od = __shfl_xor_sync(FULLM, kd, j);
            int   oi = __shfl_xor_sync(FULLM, ki, j);
            bool lower    = (lane & j) == 0;
            bool up       = (lane & k) == 0;
            bool keep_min = (lower == up);
            bool less     = (od < kd) || (od == kd && oi < ki);
            if (less == keep_min) { kd = od; ki = oi; }
        }
    }
}

// ---- search: one warp per query, collect-then-sort top-K -----------------

__global__ __launch_bounds__(TPB) void k_search(
    const float* __restrict__ pos, float* __restrict__ out, int M)
{
    __shared__ float2 s_hits[QPB][KNB];   // per-warp hit buffer

    const int b    = blockIdx.y;
    const int warp = threadIdx.x >> 5;
    const int lane = threadIdx.x & 31;

    const int n = blockIdx.x * QPB + warp;
    const float* gp = pos + (size_t)b * NGR * 3;
    float qx = gp[3 * n + 0], qy = gp[3 * n + 1], qz = gp[3 * n + 2];
    float qw = __fadd_rn(__fadd_rn(__fmul_rn(qx, qx), __fmul_rn(qy, qy)),
                         __fmul_rn(qz, qz));

    const int x0 = clamp_x(qx - 10.01f),  x1 = clamp_x(qx + 10.01f);
    const int y0 = clamp_yz(qy - 10.01f), y1 = clamp_yz(qy + 10.01f);
    const int z0 = clamp_yz(qz - 10.01f), z1 = clamp_yz(qz + 10.01f);

    const float INF = __int_as_float(0x7f800000);
    float kd = INF;          // sorted list (only live in insert mode / at end)
    int   ki = lane;
    int   cnt = 0;
    bool  ins_mode = false;  // fallback: sorted-insertion after >32 hits

    const unsigned below = (1u << lane) - 1u;

    for (int cz = z0; cz <= z1; ++cz) {
        for (int cy = y0; cy <= y1; ++cy) {
            int rowbase = b * NCELL + (cz * NCYZ + cy) * NCX;
            int s = g_cellstart[rowbase + x0];
            int e = g_cellstart[rowbase + x1 + 1];  // contiguous x-run
            for (int t0 = s; t0 < e; t0 += 32) {
                int  t   = t0 + lane;
                bool act = t < e;
                float4 c = act ? g_sorted[t]
                               : make_float4(0.f, 0.f, 0.f, 1e30f);
                // Reference-rounded GEMM-form d2 (no FMA, fixed association).
                float m1 = __fmul_rn(qx, c.x);
                float m2 = __fmul_rn(qy, c.y);
                float m3 = __fmul_rn(qz, c.z);
                float dote = __fadd_rn(__fadd_rn(m1, m2), m3);
                float tt   = __fadd_rn(qw, c.w);
                float d2   = __fsub_rn(tt, __fmul_rn(2.0f, dote));
                float de = INF;
                int   jl = n;  // self => excluded
                bool  hit = false;
                if (act && d2 <= 100.001f) {
                    de = __fsqrt_rn(fmaxf(d2, 0.0f));
                    jl = g_sidx[t];
                    hit = (de <= 10.0f) && (jl != n);
                }
                unsigned emask = __ballot_sync(FULLM, hit);
                if (!emask) continue;
                int h = __popc(emask);

                if (!ins_mode) {
                    if (cnt + h <= KNB) {
                        // Fast path: scatter hits to smem slots, no shuffles.
                        if (hit) {
                            int rank = __popc(emask & below);
                            s_hits[warp][cnt + rank] =
                                make_float2(de, __int_as_float(jl));
                        }
                        cnt += h;
                        continue;
                    }
                    // Overflow: sort what we have, switch to insertion mode.
                    __syncwarp();
                    float2 v = s_hits[warp][lane];
                    kd = (lane < cnt) ? v.x : INF;
                    ki = (lane < cnt) ? __float_as_int(v.y) : lane;
                    warp_sort32(kd, ki, lane);
                    ins_mode = true;
                }
                // Insertion path (R8): lex (dist, idx) sorted insert per hit.
                while (emask) {
                    int src = __ffs(emask) - 1;
                    emask &= emask - 1;
                    float d  = __shfl_sync(FULLM, de, src);
                    int   jj = __shfl_sync(FULLM, jl, src);
                    int p = __popc(__ballot_sync(FULLM,
                                (kd < d) || (kd == d && ki < jj)));
                    float sd = __shfl_up_sync(FULLM, kd, 1);
                    int   si = __shfl_up_sync(FULLM, ki, 1);
                    if (p < 32) {
                        if (lane == p)     { kd = d;  ki = jj; }
                        else if (lane > p) { kd = sd; ki = si; }
                    }
                }
            }
        }
    }

    if (!ins_mode) {
        __syncwarp();
        float2 v = s_hits[warp][lane];
        kd = (lane < cnt) ? v.x : INF;
        ki = (lane < cnt) ? __float_as_int(v.y) : lane;
        warp_sort32(kd, ki, lane);
    }

    // Emit: lane l writes slot l. Invalid (kd==INF pad) -> zeros.
    const int  g    = b * NGR + n;
    const long base = (long)g * KNB;
    float* rowp = out;
    float* colp = out + (long)M;
    float* wp   = out + 2L * (long)M;
    float* vp   = out + 3L * (long)M;

    float rv = 0.0f, cv = 0.0f, wv = 0.0f, vv = 0.0f;
    if (kd < INF) {
        float cxp = gp[3 * ki + 0], cyp = gp[3 * ki + 1], czp = gp[3 * ki + 2];
        float dx = __fsub_rn(qx, cxp);
        float dy = __fsub_rn(qy, cyp);
        float dz = __fsub_rn(qz, czp);
        float ss = __fadd_rn(__fadd_rn(__fmul_rn(dx, dx), __fmul_rn(dy, dy)),
                             __fmul_rn(dz, dz));
        wv = __fsqrt_rn(ss);
        rv = (float)g;
        cv = (float)(b * NGR + ki);
        vv = 1.0f;
    }
    rowp[base + lane] = rv;
    colp[base + lane] = cv;
    wp[base + lane]   = wv;
    vp[base + lane]   = vv;
}

// ---- launch --------------------------------------------------------------

extern "C" void kernel_launch(void* const* d_in, const int* in_sizes, int n_in,
                              void* d_out, int out_size) {
    const float* pos = (const float*)d_in[0];
    (void)in_sizes; (void)n_in;
    float* out = (float*)d_out;
    int M = out_size / 4;

    k_build<<<BGR, BT>>>(pos);
    dim3 grid(NGR / QPB, BGR, 1);
    k_search<<<grid, TPB>>>(pos, out, M);
}

// round 13
// speedup vs baseline: 1.2624x; 1.2624x over previous
#include <cuda_runtime.h>
#include <cuda_bf16.h>

// DenseRadiusGraph R11: single kernel, per-CTA shared-memory cell list.
// Grid = 55 x 16 = 880 CTAs (one resident wave at 6 CTAs/SM x 148 SMs);
// each CTA builds graph b's cell list in smem (~1.5us, fully independent,
// no inter-CTA sync), then its 8 warps each search 4-5 queries from smem.
// Eliminates the separate build kernel + launch gap (~5.5us).
//
// Search body is R8-verbatim (32-reg insertion top-K): candidates now come
// from smem as {x,y,z, idx_bits}; sq is recomputed per candidate with the
// same reference rounding (bit-identical to the stored value), so selection
// numerics are unchanged. Ties broken lexicographically by (dist, index) ==
// top_k lowest-index-first, independent of nondeterministic scatter order.
// w = direct-form distance, non-FMA.

#define BGR   16
#define NGR   2048
#define KNB   32
#define NCX   10
#define NCYZ  5
#define NCELL (NCX * NCYZ * NCYZ)   // 250
#define TPB   256
#define WPB   (TPB / 32)            // 8 warps
#define GX    55                    // CTAs per graph (55*16=880 <= 888)
#define NPT   (NGR / TPB)           // 8 nodes per thread in build

#define FULLM 0xffffffffu

__device__ __forceinline__ int clamp_x(float v) {
    int c = __float2int_rd(v * 0.1f);            // /10
    return min(NCX - 1, max(0, c));
}
__device__ __forceinline__ int clamp_yz(float v) {
    int c = __float2int_rd(v * 0.05f);           // /20
    return min(NCYZ - 1, max(0, c));
}

__global__ __launch_bounds__(TPB, 6) void k_fused(
    const float* __restrict__ pos, float* __restrict__ out, int M)
{
    __shared__ float4 s_pts[NGR];        // {x, y, z, idx_bits} cell-sorted
    __shared__ int    s_start[NCELL + 1];
    __shared__ int    s_cur[NCELL];      // histogram, then scatter cursor
    __shared__ int    s_woff[WPB];

    const int b    = blockIdx.y;
    const int t    = threadIdx.x;
    const int warp = t >> 5;
    const int lane = t & 31;
    const float* gp = pos + (size_t)b * NGR * 3;

    // ---- Per-CTA build: histogram -> scan -> scatter (all smem) ---------
    for (int i = t; i < NCELL; i += TPB) s_cur[i] = 0;
    __syncthreads();

    float px[NPT], py[NPT], pz[NPT];
    int   cid[NPT];
    #pragma unroll
    for (int k = 0; k < NPT; ++k) {
        int n = t + k * TPB;
        px[k] = gp[3 * n + 0];
        py[k] = gp[3 * n + 1];
        pz[k] = gp[3 * n + 2];
        cid[k] = (clamp_yz(pz[k]) * NCYZ + clamp_yz(py[k])) * NCX + clamp_x(px[k]);
        atomicAdd(&s_cur[cid[k]], 1);
    }
    __syncthreads();

    // Exclusive scan of 250 counters: 8 warp shfl scans + 1 top scan.
    {
        int v = (t < NCELL) ? s_cur[t] : 0;
        int incl = v;
        #pragma unroll
        for (int d = 1; d < 32; d <<= 1) {
            int u = __shfl_up_sync(FULLM, incl, d);
            if (lane >= d) incl += u;
        }
        if (lane == 31) s_woff[warp] = incl;
        __syncthreads();
        if (warp == 0 && lane < WPB) {
            int w = s_woff[lane];
            int iw = w;
            #pragma unroll
            for (int d = 1; d < WPB; d <<= 1) {
                int u = __shfl_up_sync(0x000000ffu, iw, d);
                if (lane >= d) iw += u;
            }
            s_woff[lane] = iw - w;   // exclusive warp offset
        }
        __syncthreads();
        if (t < NCELL) {
            int excl = incl - v + s_woff[warp];
            s_start[t] = excl;
            s_cur[t]   = excl;
        }
        if (t == 0) s_start[NCELL] = NGR;
    }
    __syncthreads();

    // Scatter: {x,y,z, idx_bits} into cell-sorted smem.
    #pragma unroll
    for (int k = 0; k < NPT; ++k) {
        int slot = atomicAdd(&s_cur[cid[k]], 1);
        s_pts[slot] = make_float4(px[k], py[k], pz[k],
                                  __int_as_float(t + k * TPB));
    }
    __syncthreads();

    // ---- Search: each warp handles queries gw, gw+440, ... --------------
    const float INF = __int_as_float(0x7f800000);
    const int gw = blockIdx.x * WPB + warp;       // [0, GX*WPB)

    for (int n = gw; n < NGR; n += GX * WPB) {
        float qx = gp[3 * n + 0], qy = gp[3 * n + 1], qz = gp[3 * n + 2];
        float qw = __fadd_rn(__fadd_rn(__fmul_rn(qx, qx), __fmul_rn(qy, qy)),
                             __fmul_rn(qz, qz));

        const int x0 = clamp_x(qx - 10.01f),  x1 = clamp_x(qx + 10.01f);
        const int y0 = clamp_yz(qy - 10.01f), y1 = clamp_yz(qy + 10.01f);
        const int z0 = clamp_yz(qz - 10.01f), z1 = clamp_yz(qz + 10.01f);

        float kd = INF;   // lane l holds l-th smallest (dist, idx)
        int   ki = -1;

        for (int cz = z0; cz <= z1; ++cz) {
            for (int cy = y0; cy <= y1; ++cy) {
                int rowbase = (cz * NCYZ + cy) * NCX;
                int s = s_start[rowbase + x0];
                int e = s_start[rowbase + x1 + 1];  // contiguous x-run
                for (int t0 = s; t0 < e; t0 += 32) {
                    int  tt2 = t0 + lane;
                    bool act = tt2 < e;
                    float4 c = act ? s_pts[tt2]
                                   : make_float4(0.f, 0.f, 0.f, 0.f);
                    // sq recomputed with reference rounding (bit-identical
                    // to the value the reference computes for this node).
                    float cw = __fadd_rn(__fadd_rn(__fmul_rn(c.x, c.x),
                                                   __fmul_rn(c.y, c.y)),
                                         __fmul_rn(c.z, c.z));
                    // Reference-rounded GEMM-form d2 (no FMA, fixed assoc).
                    float m1 = __fmul_rn(qx, c.x);
                    float m2 = __fmul_rn(qy, c.y);
                    float m3 = __fmul_rn(qz, c.z);
                    float dote = __fadd_rn(__fadd_rn(m1, m2), m3);
                    float ts   = __fadd_rn(qw, cw);
                    float d2   = __fsub_rn(ts, __fmul_rn(2.0f, dote));
                    float de = INF;
                    int   jl = n;  // self => excluded
                    if (act && d2 <= 100.001f) {
                        de = __fsqrt_rn(fmaxf(d2, 0.0f));
                        jl = __float_as_int(c.w);
                    }
                    unsigned emask =
                        __ballot_sync(FULLM, (de <= 10.0f) && (jl != n));
                    while (emask) {
                        int src = __ffs(emask) - 1;
                        emask &= emask - 1;
                        float d  = __shfl_sync(FULLM, de, src);
                        int   jj = __shfl_sync(FULLM, jl, src);
                        int p = __popc(__ballot_sync(FULLM,
                                    (kd < d) || (kd == d && ki < jj)));
                        float sd = __shfl_up_sync(FULLM, kd, 1);
                        int   si = __shfl_up_sync(FULLM, ki, 1);
                        if (p < 32) {
                            if (lane == p)     { kd = d;  ki = jj; }
                            else if (lane > p) { kd = sd; ki = si; }
                        }
                    }
                }
            }
        }

        // Emit: lane l writes slot l. Invalid -> zeros.
        const int  g    = b * NGR + n;
        const long base = (long)g * KNB;
        float* rowp = out;
        float* colp = out + (long)M;
        float* wp   = out + 2L * (long)M;
        float* vp   = out + 3L * (long)M;

        float rv = 0.0f, cv = 0.0f, wv = 0.0f, vv = 0.0f;
        if (kd < INF) {
            float cxp = gp[3 * ki + 0], cyp = gp[3 * ki + 1],
                  czp = gp[3 * ki + 2];
            float dx = __fsub_rn(qx, cxp);
            float dy = __fsub_rn(qy, cyp);
            float dz = __fsub_rn(qz, czp);
            float ss = __fadd_rn(__fadd_rn(__fmul_rn(dx, dx),
                                           __fmul_rn(dy, dy)),
                                 __fmul_rn(dz, dz));
            wv = __fsqrt_rn(ss);
            rv = (float)g;
            cv = (float)(b * NGR + ki);
            vv = 1.0f;
        }
        rowp[base + lane] = rv;
        colp[base + lane] = cv;
        wp[base + lane]   = wv;
        vp[base + lane]   = vv;
    }
}

// ---- launch --------------------------------------------------------------

extern "C" void kernel_launch(void* const* d_in, const int* in_sizes, int n_in,
                              void* d_out, int out_size) {
    const float* pos = (const float*)d_in[0];
    (void)in_sizes; (void)n_in;
    float* out = (float*)d_out;
    int M = out_size / 4;

    dim3 grid(GX, BGR, 1);
    k_fused<<<grid, TPB>>>(pos, out, M);
}

// round 15
// speedup vs baseline: 1.3164x; 1.0427x over previous
#include <cuda_runtime.h>
#include <cuda_bf16.h>

// DenseRadiusGraph R12 = R8 structure with a wider build kernel.
//  - k_search: byte-identical logic to R8 (32-reg insertion top-K, proven
//    25.7us @ 75% occ across three rounds) + __launch_bounds__(256,8) pin
//    (it compiles at exactly 32 regs = the 8-CTA cap, so no spill).
//  - k_build: BT 512 -> 1024 (NPT=2): 32 warps/SM on the 16 active SMs,
//    doubling latency hiding of the load/atomic/scatter phases.
//
// Cells: x side 10 (10 cells), y/z side 20 (5 cells) => 250 cells/graph.
// Numerics unchanged since R5: selection/ordering uses the reference's
// GEMM-form distance with plain fp32 rounding (no FMA, fixed association);
// ties broken lexicographically by (dist, index) == top_k lowest-index-first,
// independent of the nondeterministic scatter order. w = direct-form, non-FMA.

#define BGR   16
#define NGR   2048
#define KNB   32
#define NCX   10
#define NCYZ  5
#define NCELL (NCX * NCYZ * NCYZ)   // 250
#define TPB   256
#define QPB   (TPB / 32)
#define BT    1024                   // build threads per block
#define NPT   (NGR / BT)             // 2 nodes per build thread

#define FULLM 0xffffffffu

// Scratch (device globals: no allocation allowed).
__device__ float4 g_sorted[BGR * NGR];          // cell-sorted {x,y,z,sq}
__device__ int    g_sidx[BGR * NGR];            // original local index
__device__ int    g_cellstart[BGR * NCELL + 1]; // absolute offsets (+sentinel)

__device__ __forceinline__ int clamp_x(float v) {
    int c = __float2int_rd(v * 0.1f);            // /10
    return min(NCX - 1, max(0, c));
}
__device__ __forceinline__ int clamp_yz(float v) {
    int c = __float2int_rd(v * 0.05f);           // /20
    return min(NCYZ - 1, max(0, c));
}

// ---- build: one CTA per graph, BT=1024, warp-shuffle scan ----------------

__global__ __launch_bounds__(BT) void k_build(const float* __restrict__ pos) {
    __shared__ int s_cnt[NCELL];
    __shared__ int s_woff[BT / 32];   // 32 per-warp scan offsets
    __shared__ int s_cur[NCELL];

    const int b    = blockIdx.x;
    const int t    = threadIdx.x;
    const int warp = t >> 5;
    const int lane = t & 31;
    const float* gp = pos + (size_t)b * NGR * 3;

    if (t < NCELL) s_cnt[t] = 0;
    __syncthreads();

    // Phase 1: load nodes, compute cell ids, shared histogram.
    float px[NPT], py[NPT], pz[NPT];
    int   cid[NPT];
    #pragma unroll
    for (int k = 0; k < NPT; ++k) {
        int n = t + k * BT;
        px[k] = gp[3 * n + 0];
        py[k] = gp[3 * n + 1];
        pz[k] = gp[3 * n + 2];
        cid[k] = (clamp_yz(pz[k]) * NCYZ + clamp_yz(py[k])) * NCX + clamp_x(px[k]);
        atomicAdd(&s_cnt[cid[k]], 1);
    }
    __syncthreads();

    // Phase 2: exclusive scan of 250 counters (warp shfl scans + 1 top scan).
    int v = (t < NCELL) ? s_cnt[t] : 0;
    int incl = v;
    #pragma unroll
    for (int d = 1; d < 32; d <<= 1) {
        int u = __shfl_up_sync(FULLM, incl, d);
        if (lane >= d) incl += u;
    }
    if (lane == 31) s_woff[warp] = incl;
    __syncthreads();
    if (warp == 0) {
        int w = s_woff[lane];        // 32 warp totals
        int iw = w;
        #pragma unroll
        for (int d = 1; d < 32; d <<= 1) {
            int u = __shfl_up_sync(FULLM, iw, d);
            if (lane >= d) iw += u;
        }
        s_woff[lane] = iw - w;       // exclusive warp offset
    }
    __syncthreads();
    if (t < NCELL) {
        int excl = incl - v + s_woff[warp];
        s_cur[t] = excl;
        g_cellstart[b * NCELL + t] = b * NGR + excl;
    }
    if (b == 0 && t == 0) g_cellstart[BGR * NCELL] = BGR * NGR;
    __syncthreads();

    // Phase 3: scatter via shared atomic cursors.
    const int base = b * NGR;
    #pragma unroll
    for (int k = 0; k < NPT; ++k) {
        int slot = base + atomicAdd(&s_cur[cid[k]], 1);
        float sq = __fadd_rn(__fadd_rn(__fmul_rn(px[k], px[k]),
                                       __fmul_rn(py[k], py[k])),
                             __fmul_rn(pz[k], pz[k]));
        g_sorted[slot] = make_float4(px[k], py[k], pz[k], sq);
        g_sidx[slot]   = t + k * BT;
    }
}

// ---- search: one warp per query, 32-bit distributed top-K (R8, frozen) ---

__global__ __launch_bounds__(TPB, 8) void k_search(
    const float* __restrict__ pos, float* __restrict__ out, int M)
{
    const int b    = blockIdx.y;
    const int warp = threadIdx.x >> 5;
    const int lane = threadIdx.x & 31;

    const int n = blockIdx.x * QPB + warp;
    const float* gp = pos + (size_t)b * NGR * 3;
    float qx = gp[3 * n + 0], qy = gp[3 * n + 1], qz = gp[3 * n + 2];
    float qw = __fadd_rn(__fadd_rn(__fmul_rn(qx, qx), __fmul_rn(qy, qy)),
                         __fmul_rn(qz, qz));

    const int x0 = clamp_x(qx - 10.01f),  x1 = clamp_x(qx + 10.01f);
    const int y0 = clamp_yz(qy - 10.01f), y1 = clamp_yz(qy + 10.01f);
    const int z0 = clamp_yz(qz - 10.01f), z1 = clamp_yz(qz + 10.01f);

    const float INF = __int_as_float(0x7f800000);
    float kd = INF;   // lane l holds l-th smallest (dist, idx)
    int   ki = -1;

    for (int cz = z0; cz <= z1; ++cz) {
        for (int cy = y0; cy <= y1; ++cy) {
            int rowbase = b * NCELL + (cz * NCYZ + cy) * NCX;
            int s = g_cellstart[rowbase + x0];
            int e = g_cellstart[rowbase + x1 + 1];  // contiguous x-run
            for (int t0 = s; t0 < e; t0 += 32) {
                int  t   = t0 + lane;
                bool act = t < e;
                float4 c = act ? g_sorted[t] : make_float4(0.f, 0.f, 0.f, 1e30f);
                // Reference-rounded GEMM-form d2 (no FMA, fixed association).
                float m1 = __fmul_rn(qx, c.x);
                float m2 = __fmul_rn(qy, c.y);
                float m3 = __fmul_rn(qz, c.z);
                float dote = __fadd_rn(__fadd_rn(m1, m2), m3);
                float tt   = __fadd_rn(qw, c.w);
                float d2   = __fsub_rn(tt, __fmul_rn(2.0f, dote));
                float de = INF;
                int   jl = n;  // self => excluded
                if (act && d2 <= 100.001f) {
                    de = __fsqrt_rn(fmaxf(d2, 0.0f));
                    jl = g_sidx[t];
                }
                unsigned emask = __ballot_sync(FULLM, (de <= 10.0f) && (jl != n));
                while (emask) {
                    int src = __ffs(emask) - 1;
                    emask &= emask - 1;
                    float d  = __shfl_sync(FULLM, de, src);
                    int   jj = __shfl_sync(FULLM, jl, src);
                    // entries strictly before (d,jj) lexicographically stay put
                    int p = __popc(__ballot_sync(FULLM,
                                (kd < d) || (kd == d && ki < jj)));
                    float sd = __shfl_up_sync(FULLM, kd, 1);
                    int   si = __shfl_up_sync(FULLM, ki, 1);
                    if (p < 32) {
                        if (lane == p)     { kd = d;  ki = jj; }
                        else if (lane > p) { kd = sd; ki = si; }
                    }
                }
            }
        }
    }

    // Emit: lane l writes slot l. Invalid -> zeros.
    const int  g    = b * NGR + n;
    const long base = (long)g * KNB;
    float* rowp = out;
    float* colp = out + (long)M;
    float* wp   = out + 2L * (long)M;
    float* vp   = out + 3L * (long)M;

    float rv = 0.0f, cv = 0.0f, wv = 0.0f, vv = 0.0f;
    if (kd < INF) {
        float cxp = gp[3 * ki + 0], cyp = gp[3 * ki + 1], czp = gp[3 * ki + 2];
        float dx = __fsub_rn(qx, cxp);
        float dy = __fsub_rn(qy, cyp);
        float dz = __fsub_rn(qz, czp);
        float ss = __fadd_rn(__fadd_rn(__fmul_rn(dx, dx), __fmul_rn(dy, dy)),
                             __fmul_rn(dz, dz));
        wv = __fsqrt_rn(ss);
        rv = (float)g;
        cv = (float)(b * NGR + ki);
        vv = 1.0f;
    }
    rowp[base + lane] = rv;
    colp[base + lane] = cv;
    wp[base + lane]   = wv;
    vp[base + lane]   = vv;
}

// ---- launch --------------------------------------------------------------

extern "C" void kernel_launch(void* const* d_in, const int* in_sizes, int n_in,
                              void* d_out, int out_size) {
    const float* pos = (const float*)d_in[0];
    (void)in_sizes; (void)n_in;
    float* out = (float*)d_out;
    int M = out_size / 4;

    k_build<<<BGR, BT>>>(pos);
    dim3 grid(NGR / QPB, BGR, 1);
    k_search<<<grid, TPB>>>(pos, out, M);
}

// round 17
// speedup vs baseline: 1.4020x; 1.0650x over previous
#include <cuda_runtime.h>
#include <cuda_bf16.h>

// DenseRadiusGraph R13 = R12 + Programmatic Dependent Launch (PDL).
// k_search is prelaunched while k_build drains; it runs its build-independent
// preamble (query loads from pos, sq, cell ranges), then blocks at
// cudaGridDependencySynchronize() before the first g_cellstart/g_sorted read.
// k_build triggers completion after its last store. Collapses the ~2us
// kernel-boundary gap; search body itself is byte-identical to R8/R12
// (32-reg insertion top-K, 25.5us @ 75% occ, frozen for four rounds).
//
// Cells: x side 10 (10 cells), y/z side 20 (5 cells) => 250 cells/graph.
// Numerics unchanged since R5: selection/ordering uses the reference's
// GEMM-form distance with plain fp32 rounding (no FMA, fixed association);
// ties broken lexicographically by (dist, index) == top_k lowest-index-first,
// independent of the nondeterministic scatter order. w = direct-form, non-FMA.

#define BGR   16
#define NGR   2048
#define KNB   32
#define NCX   10
#define NCYZ  5
#define NCELL (NCX * NCYZ * NCYZ)   // 250
#define TPB   256
#define QPB   (TPB / 32)
#define BT    1024                   // build threads per block
#define NPT   (NGR / BT)             // 2 nodes per build thread

#define FULLM 0xffffffffu

// Scratch (device globals: no allocation allowed).
__device__ float4 g_sorted[BGR * NGR];          // cell-sorted {x,y,z,sq}
__device__ int    g_sidx[BGR * NGR];            // original local index
__device__ int    g_cellstart[BGR * NCELL + 1]; // absolute offsets (+sentinel)

__device__ __forceinline__ int clamp_x(float v) {
    int c = __float2int_rd(v * 0.1f);            // /10
    return min(NCX - 1, max(0, c));
}
__device__ __forceinline__ int clamp_yz(float v) {
    int c = __float2int_rd(v * 0.05f);           // /20
    return min(NCYZ - 1, max(0, c));
}

// ---- build: one CTA per graph, BT=1024, warp-shuffle scan ----------------

__global__ __launch_bounds__(BT) void k_build(const float* __restrict__ pos) {
    __shared__ int s_cnt[NCELL];
    __shared__ int s_woff[BT / 32];   // 32 per-warp scan offsets
    __shared__ int s_cur[NCELL];

    const int b    = blockIdx.x;
    const int t    = threadIdx.x;
    const int warp = t >> 5;
    const int lane = t & 31;
    const float* gp = pos + (size_t)b * NGR * 3;

    if (t < NCELL) s_cnt[t] = 0;
    __syncthreads();

    // Phase 1: load nodes, compute cell ids, shared histogram.
    float px[NPT], py[NPT], pz[NPT];
    int   cid[NPT];
    #pragma unroll
    for (int k = 0; k < NPT; ++k) {
        int n = t + k * BT;
        px[k] = gp[3 * n + 0];
        py[k] = gp[3 * n + 1];
        pz[k] = gp[3 * n + 2];
        cid[k] = (clamp_yz(pz[k]) * NCYZ + clamp_yz(py[k])) * NCX + clamp_x(px[k]);
        atomicAdd(&s_cnt[cid[k]], 1);
    }
    __syncthreads();

    // Phase 2: exclusive scan of 250 counters (warp shfl scans + 1 top scan).
    int v = (t < NCELL) ? s_cnt[t] : 0;
    int incl = v;
    #pragma unroll
    for (int d = 1; d < 32; d <<= 1) {
        int u = __shfl_up_sync(FULLM, incl, d);
        if (lane >= d) incl += u;
    }
    if (lane == 31) s_woff[warp] = incl;
    __syncthreads();
    if (warp == 0) {
        int w = s_woff[lane];        // 32 warp totals
        int iw = w;
        #pragma unroll
        for (int d = 1; d < 32; d <<= 1) {
            int u = __shfl_up_sync(FULLM, iw, d);
            if (lane >= d) iw += u;
        }
        s_woff[lane] = iw - w;       // exclusive warp offset
    }
    __syncthreads();
    if (t < NCELL) {
        int excl = incl - v + s_woff[warp];
        s_cur[t] = excl;
        g_cellstart[b * NCELL + t] = b * NGR + excl;
    }
    if (b == 0 && t == 0) g_cellstart[BGR * NCELL] = BGR * NGR;
    __syncthreads();

    // Phase 3: scatter via shared atomic cursors.
    const int base = b * NGR;
    #pragma unroll
    for (int k = 0; k < NPT; ++k) {
        int slot = base + atomicAdd(&s_cur[cid[k]], 1);
        float sq = __fadd_rn(__fadd_rn(__fmul_rn(px[k], px[k]),
                                       __fmul_rn(py[k], py[k])),
                             __fmul_rn(pz[k], pz[k]));
        g_sorted[slot] = make_float4(px[k], py[k], pz[k], sq);
        g_sidx[slot]   = t + k * BT;
    }

    // PDL: all our stores are issued; allow the dependent search grid to
    // proceed (visibility guaranteed at the secondary's sync point).
    cudaTriggerProgrammaticLaunchCompletion();
}

// ---- search: one warp per query, 32-bit distributed top-K (frozen body) --

__global__ __launch_bounds__(TPB, 8) void k_search(
    const float* __restrict__ pos, float* __restrict__ out, int M)
{
    const int b    = blockIdx.y;
    const int warp = threadIdx.x >> 5;
    const int lane = threadIdx.x & 31;

    // Build-independent preamble (reads only harness input `pos`).
    const int n = blockIdx.x * QPB + warp;
    const float* gp = pos + (size_t)b * NGR * 3;
    float qx = gp[3 * n + 0], qy = gp[3 * n + 1], qz = gp[3 * n + 2];
    float qw = __fadd_rn(__fadd_rn(__fmul_rn(qx, qx), __fmul_rn(qy, qy)),
                         __fmul_rn(qz, qz));

    const int x0 = clamp_x(qx - 10.01f),  x1 = clamp_x(qx + 10.01f);
    const int y0 = clamp_yz(qy - 10.01f), y1 = clamp_yz(qy + 10.01f);
    const int z0 = clamp_yz(qz - 10.01f), z1 = clamp_yz(qz + 10.01f);

    // Wait for k_build's cell list to be visible.
    cudaGridDependencySynchronize();

    const float INF = __int_as_float(0x7f800000);
    float kd = INF;   // lane l holds l-th smallest (dist, idx)
    int   ki = -1;

    for (int cz = z0; cz <= z1; ++cz) {
        for (int cy = y0; cy <= y1; ++cy) {
            int rowbase = b * NCELL + (cz * NCYZ + cy) * NCX;
            int s = g_cellstart[rowbase + x0];
            int e = g_cellstart[rowbase + x1 + 1];  // contiguous x-run
            for (int t0 = s; t0 < e; t0 += 32) {
                int  t   = t0 + lane;
                bool act = t < e;
                float4 c = act ? g_sorted[t] : make_float4(0.f, 0.f, 0.f, 1e30f);
                // Reference-rounded GEMM-form d2 (no FMA, fixed association).
                float m1 = __fmul_rn(qx, c.x);
                float m2 = __fmul_rn(qy, c.y);
                float m3 = __fmul_rn(qz, c.z);
                float dote = __fadd_rn(__fadd_rn(m1, m2), m3);
                float tt   = __fadd_rn(qw, c.w);
                float d2   = __fsub_rn(tt, __fmul_rn(2.0f, dote));
                float de = INF;
                int   jl = n;  // self => excluded
                if (act && d2 <= 100.001f) {
                    de = __fsqrt_rn(fmaxf(d2, 0.0f));
                    jl = g_sidx[t];
                }
                unsigned emask = __ballot_sync(FULLM, (de <= 10.0f) && (jl != n));
                while (emask) {
                    int src = __ffs(emask) - 1;
                    emask &= emask - 1;
                    float d  = __shfl_sync(FULLM, de, src);
                    int   jj = __shfl_sync(FULLM, jl, src);
                    // entries strictly before (d,jj) lexicographically stay put
                    int p = __popc(__ballot_sync(FULLM,
                                (kd < d) || (kd == d && ki < jj)));
                    float sd = __shfl_up_sync(FULLM, kd, 1);
                    int   si = __shfl_up_sync(FULLM, ki, 1);
                    if (p < 32) {
                        if (lane == p)     { kd = d;  ki = jj; }
                        else if (lane > p) { kd = sd; ki = si; }
                    }
                }
            }
        }
    }

    // Emit: lane l writes slot l. Invalid -> zeros.
    const int  g    = b * NGR + n;
    const long base = (long)g * KNB;
    float* rowp = out;
    float* colp = out + (long)M;
    float* wp   = out + 2L * (long)M;
    float* vp   = out + 3L * (long)M;

    float rv = 0.0f, cv = 0.0f, wv = 0.0f, vv = 0.0f;
    if (kd < INF) {
        float cxp = gp[3 * ki + 0], cyp = gp[3 * ki + 1], czp = gp[3 * ki + 2];
        float dx = __fsub_rn(qx, cxp);
        float dy = __fsub_rn(qy, cyp);
        float dz = __fsub_rn(qz, czp);
        float ss = __fadd_rn(__fadd_rn(__fmul_rn(dx, dx), __fmul_rn(dy, dy)),
                             __fmul_rn(dz, dz));
        wv = __fsqrt_rn(ss);
        rv = (float)g;
        cv = (float)(b * NGR + ki);
        vv = 1.0f;
    }
    rowp[base + lane] = rv;
    colp[base + lane] = cv;
    wp[base + lane]   = wv;
    vp[base + lane]   = vv;
}

// ---- launch --------------------------------------------------------------

extern "C" void kernel_launch(void* const* d_in, const int* in_sizes, int n_in,
                              void* d_out, int out_size) {
    const float* pos = (const float*)d_in[0];
    (void)in_sizes; (void)n_in;
    float* out = (float*)d_out;
    int M = out_size / 4;

    k_build<<<BGR, BT>>>(pos);

    // Search launched with PDL: prelaunch while k_build drains; the kernel
    // blocks at cudaGridDependencySynchronize() until build's writes are
    // visible.
    cudaLaunchConfig_t cfg = {};
    cfg.gridDim  = dim3(NGR / QPB, BGR, 1);
    cfg.blockDim = dim3(TPB, 1, 1);
    cudaLaunchAttribute attr[1];
    attr[0].id = cudaLaunchAttributeProgrammaticStreamSerialization;
    attr[0].val.programmaticStreamSerializationAllowed = 1;
    cfg.attrs    = attr;
    cfg.numAttrs = 1;
    cudaLaunchKernelEx(&cfg, k_search, pos, out, M);
}